// round 9
// baseline (speedup 1.0000x reference)
#include <cuda_runtime.h>
#include <cuda_fp16.h>
#include <math_constants.h>
#include <cstdint>

#define F_IN 116
#define K2N  58          // F_IN/2
#define H 8
#define C 32
#define HC 256           // H*C
#define MAXN 50016
#define MAXE 1000000     // >= E + 3N + pad
#define NEG_SLOPE 0.2f
#define ROWS 32          // gemm rows per block
#define XSP 120          // padded shared row (16B multiple)
#define CSRB 148         // persistent CSR blocks (one per SM, co-resident)
#define CH 512           // nodes per block in scan phase (ceil(50000/512)=98 <= CSRB)

// ---------------- device scratch (no allocations allowed) ----------------
__device__ __align__(16) __half g_xt_h[(size_t)MAXN * HC]; // fp16 features; row N stays 0 (sentinel)
__device__ __align__(16) float g_as[(size_t)MAXN * H];     // alpha_src (row N = -inf sentinel)
__device__ __align__(16) float g_ad[(size_t)MAXN * H];     // alpha_dst
__device__ unsigned long long g_Wt[K2N * HC];              // W repacked into k-pairs (f32x2)
__device__ __align__(16) int g_deg[MAXN];
__device__ int g_off[MAXN + 1];                            // aligned (ceil4) offsets
__device__ int g_cur[MAXN];
__device__ __align__(16) int g_csr[MAXE];                  // src ids grouped by dst, sentinel-padded
__device__ int g_bsum[256];                                // per-block scan partials
__device__ unsigned g_bar;                                 // software grid barrier counter
__device__ int g_idx64;

// ---------------- side stream + events, created once at program start ----------------
struct HxStreams {
    cudaStream_t s2;
    cudaEvent_t evFork, evJoin;
    HxStreams() {
        cudaStreamCreateWithFlags(&s2, cudaStreamNonBlocking);
        cudaEventCreateWithFlags(&evFork, cudaEventDisableTiming);
        cudaEventCreateWithFlags(&evJoin, cudaEventDisableTiming);
    }
};
static HxStreams g_hx;

// ---------------- init: detect + zero deg + sentinel + W repack + csr prefill + bar reset ----------------
__global__ void init_kernel(const int* ei32, int n_check, const float* __restrict__ W,
                            int N, int EP) {
    int i = blockIdx.x * blockDim.x + threadIdx.x;
    if (i == 0) {
        int is64 = 1;
        for (int k = 0; k < n_check; k++)
            if (ei32[2 * k + 1] != 0) { is64 = 0; break; }
        g_idx64 = is64;
        g_bar = 0u;
    }
    if (i < N) g_deg[i] = 0;
    if (i == N) {
#pragma unroll
        for (int h = 0; h < H; h++) g_as[(size_t)N * H + h] = -CUDART_INF_F;
    }
    if (i < K2N * HC) {
        int k2 = i / HC, j = i - k2 * HC;
        unsigned int lo = __float_as_uint(W[(2 * k2) * HC + j]);
        unsigned int hi = __float_as_uint(W[(2 * k2 + 1) * HC + j]);
        g_Wt[i] = ((unsigned long long)hi << 32) | lo;
    }
    if (i < EP) g_csr[i] = N;   // sentinel prefill
}

// ---------------- fused persistent CSR build: count -> scan -> scatter ----------------
__device__ __forceinline__ int ceil4(int v) { return (v + 3) & ~3; }

__device__ __forceinline__ void grid_bar(unsigned target) {
    __syncthreads();
    if (threadIdx.x == 0) {
        __threadfence();
        atomicAdd(&g_bar, 1u);
        while (*(volatile unsigned*)&g_bar < target) { }
    }
    __syncthreads();
}

__global__ void __launch_bounds__(256, 1)
csr_build_kernel(const void* __restrict__ ei, int E, int N) {
    __shared__ int sm[256];
    int b = blockIdx.x;
    int t = threadIdx.x;
    unsigned B = gridDim.x;
    int gtid = b * 256 + t;
    int stride = (int)B * 256;
    int idx64 = g_idx64;

    // ---- phase 1: count in-degrees ----
    if (idx64) {
        const long long* pd = (const long long*)ei + (size_t)E;
        for (int i = gtid; i < E; i += stride)
            atomicAdd(&g_deg[(int)pd[i]], 1);
    } else {
        const int* pd = (const int*)ei + E;
        for (int i = gtid; i < E; i += stride)
            atomicAdd(&g_deg[pd[i]], 1);
    }
    grid_bar(B);

    // ---- phase 2a: per-block chunk sums of ceil4(deg) ----
    int c0 = b * CH;
    {
        int s = 0;
#pragma unroll
        for (int k = 0; k < CH / 256; k++) {
            int i = c0 + t + k * 256;
            if (i < N) s += ceil4(g_deg[i]);
        }
        sm[t] = s;
        __syncthreads();
        for (int o = 128; o > 0; o >>= 1) {
            if (t < o) sm[t] += sm[t + o];
            __syncthreads();
        }
        if (t == 0) g_bsum[b] = sm[0];
    }
    grid_bar(2 * B);

    // ---- phase 2b: base = sum of preceding block sums, then local scan ----
    {
        int bp = (t < b) ? g_bsum[t] : 0;   // b <= 147 < 256
        __syncthreads();
        sm[t] = bp;
        __syncthreads();
        for (int o = 128; o > 0; o >>= 1) {
            if (t < o) sm[t] += sm[t + o];
            __syncthreads();
        }
        int base = sm[0];
        __syncthreads();

        const int PT = CH / 256;            // 2 contiguous nodes per thread
        int cbase = c0 + t * PT;
        int loc[PT];
        int s = 0;
#pragma unroll
        for (int k = 0; k < PT; k++) {
            int i = cbase + k;
            loc[k] = s;
            if (i < N) s += ceil4(g_deg[i]);
        }
        sm[t] = s;
        __syncthreads();
        for (int o = 1; o < 256; o <<= 1) {
            int v = (t >= o) ? sm[t - o] : 0;
            __syncthreads();
            sm[t] += v;
            __syncthreads();
        }
        int tbase = base + ((t > 0) ? sm[t - 1] : 0);
#pragma unroll
        for (int k = 0; k < PT; k++) {
            int i = cbase + k;
            if (i < N) {
                int o = tbase + loc[k];
                g_off[i] = o;
                g_cur[i] = o;
            }
        }
        if (b == (N - 1) / CH && t == 255) g_off[N] = base + sm[255];
    }
    grid_bar(3 * B);

    // ---- phase 3: scatter src ids into CSR slots ----
    if (idx64) {
        const long long* ps = (const long long*)ei;
        const long long* pd = ps + (size_t)E;
        for (int i = gtid; i < E; i += stride) {
            int src = (int)ps[i];
            int dst = (int)pd[i];
            int pos = atomicAdd(&g_cur[dst], 1);
            g_csr[pos] = src;
        }
    } else {
        const int* ps = (const int*)ei;
        const int* pd = ps + E;
        for (int i = gtid; i < E; i += stride) {
            int src = ps[i];
            int dst = pd[i];
            int pos = atomicAdd(&g_cur[dst], 1);
            g_csr[pos] = src;
        }
    }
}

// ---------------- xt = x @ W (f32x2 FFMA2, LDS.128) + alpha_src/alpha_dst ----------------
__global__ void __launch_bounds__(256, 2)
gemm_alpha_kernel(const float* __restrict__ x,
                  const float* __restrict__ att_src,
                  const float* __restrict__ att_dst,
                  int N) {
    __shared__ __align__(16) float xs[ROWS][XSP];
    int row0 = blockIdx.x * ROWS;

    for (int i = threadIdx.x; i < ROWS * F_IN; i += 256) {
        int r = i / F_IN, k = i - r * F_IN;
        int gr = row0 + r;
        xs[r][k] = (gr < N) ? x[(size_t)gr * F_IN + k] : 0.0f;
    }
    __syncthreads();

    int j = threadIdx.x;
    unsigned long long acc[ROWS];
#pragma unroll
    for (int r = 0; r < ROWS; r++) acc[r] = 0ull;

    const unsigned long long* wt = g_Wt + j;
    for (int k4 = 0; k4 < K2N / 2; k4++) {
        unsigned long long w0 = wt[(2 * k4) * HC];
        unsigned long long w1 = wt[(2 * k4 + 1) * HC];
#pragma unroll
        for (int r = 0; r < ROWS; r++) {
            ulonglong2 a2 = *(const ulonglong2*)&xs[r][4 * k4];
            asm("fma.rn.f32x2 %0, %1, %2, %0;" : "+l"(acc[r]) : "l"(a2.x), "l"(w0));
            asm("fma.rn.f32x2 %0, %1, %2, %0;" : "+l"(acc[r]) : "l"(a2.y), "l"(w1));
        }
    }

    float asv = att_src[j];
    float adv = att_dst[j];
    int h = j >> 5;

#pragma unroll
    for (int r = 0; r < ROWS; r++) {
        float lo, hi;
        asm("mov.b64 {%0, %1}, %2;" : "=f"(lo), "=f"(hi) : "l"(acc[r]));
        float v = lo + hi;
        int gr = row0 + r;
        if (gr < N) g_xt_h[(size_t)gr * HC + j] = __float2half_rn(v);
        float ps = v * asv;
        float pd = v * adv;
#pragma unroll
        for (int o = 16; o > 0; o >>= 1) {
            ps += __shfl_xor_sync(0xffffffffu, ps, o);
            pd += __shfl_xor_sync(0xffffffffu, pd, o);
        }
        if ((j & 31) == 0 && gr < N) {
            g_as[(size_t)gr * H + h] = ps;
            g_ad[(size_t)gr * H + h] = pd;
        }
    }
}

// ---------------- fused gather-aggregate + softmax + head-mean + bias + relu ----------------
__device__ __forceinline__ void acc_row(const float4& raw, float ev, float* acc) {
    const __half2* hp = (const __half2*)&raw;
    float2 f0 = __half22float2(hp[0]);
    float2 f1 = __half22float2(hp[1]);
    float2 f2 = __half22float2(hp[2]);
    float2 f3 = __half22float2(hp[3]);
    acc[0] = fmaf(ev, f0.x, acc[0]); acc[1] = fmaf(ev, f0.y, acc[1]);
    acc[2] = fmaf(ev, f1.x, acc[2]); acc[3] = fmaf(ev, f1.y, acc[3]);
    acc[4] = fmaf(ev, f2.x, acc[4]); acc[5] = fmaf(ev, f2.y, acc[5]);
    acc[6] = fmaf(ev, f3.x, acc[6]); acc[7] = fmaf(ev, f3.y, acc[7]);
}

__global__ void agg_kernel(const float* __restrict__ bias,
                           float* __restrict__ out, int N) {
    int gw = (blockIdx.x * blockDim.x + threadIdx.x) >> 5;
    int lane = threadIdx.x & 31;
    if (gw >= N) return;
    int n = gw;
    int h = lane >> 2;

    float ad_h = g_ad[(size_t)n * H + h];

    // self loop
    float a = g_as[(size_t)n * H + h] + ad_h;
    a = (a > 0.0f) ? a : NEG_SLOPE * a;
    float e = __expf(a);
    float s = e;

    float acc[8] = {0, 0, 0, 0, 0, 0, 0, 0};
    {
        float4 raw = ((const float4*)(g_xt_h + (size_t)n * HC))[lane];
        acc_row(raw, e, acc);
    }

    int beg = g_off[n];
    int end = g_off[n + 1];     // ceil4-aligned; padding = sentinel entries (exp=0, zero row)
    for (int p = beg; p < end; p += 4) {
        int4 sv = *(const int4*)(g_csr + p);
        float a0 = g_as[(size_t)sv.x * H + h] + ad_h;
        float a1 = g_as[(size_t)sv.y * H + h] + ad_h;
        float a2 = g_as[(size_t)sv.z * H + h] + ad_h;
        float a3 = g_as[(size_t)sv.w * H + h] + ad_h;
        a0 = (a0 > 0.0f) ? a0 : NEG_SLOPE * a0;
        a1 = (a1 > 0.0f) ? a1 : NEG_SLOPE * a1;
        a2 = (a2 > 0.0f) ? a2 : NEG_SLOPE * a2;
        a3 = (a3 > 0.0f) ? a3 : NEG_SLOPE * a3;
        float e0 = __expf(a0);
        float e1 = __expf(a1);
        float e2 = __expf(a2);
        float e3 = __expf(a3);
        s += (e0 + e1) + (e2 + e3);
        float4 r0 = ((const float4*)(g_xt_h + (size_t)sv.x * HC))[lane];
        float4 r1 = ((const float4*)(g_xt_h + (size_t)sv.y * HC))[lane];
        float4 r2 = ((const float4*)(g_xt_h + (size_t)sv.z * HC))[lane];
        float4 r3 = ((const float4*)(g_xt_h + (size_t)sv.w * HC))[lane];
        acc_row(r0, e0, acc);
        acc_row(r1, e1, acc);
        acc_row(r2, e2, acc);
        acc_row(r3, e3, acc);
    }

    float inv = 1.0f / (s + 1e-16f);
    float r[8];
#pragma unroll
    for (int i = 0; i < 8; i++) r[i] = acc[i] * inv;

    // sum over heads: butterfly across lanes differing in bits 2..4 (same lane&3)
#pragma unroll
    for (int i = 0; i < 8; i++) {
        r[i] += __shfl_xor_sync(0xffffffffu, r[i], 4);
        r[i] += __shfl_xor_sync(0xffffffffu, r[i], 8);
        r[i] += __shfl_xor_sync(0xffffffffu, r[i], 16);
    }

    if (lane < 4) {
        float o[8];
#pragma unroll
        for (int i = 0; i < 8; i++) {
            float v = r[i] * 0.125f + bias[lane * 8 + i];
            o[i] = (v > 0.0f) ? v : 0.0f;
        }
        float4* orow = (float4*)(out + (size_t)n * C + lane * 8);
        orow[0] = make_float4(o[0], o[1], o[2], o[3]);
        orow[1] = make_float4(o[4], o[5], o[6], o[7]);
    }
}

// ---------------- launch: 4 kernels, fork-join — CSR build || GEMM ----------------
extern "C" void kernel_launch(void* const* d_in, const int* in_sizes, int n_in,
                              void* d_out, int out_size) {
    const float* x       = (const float*)d_in[0];
    const void*  ei      = d_in[1];
    const float* W       = (const float*)d_in[2];
    const float* att_src = (const float*)d_in[3];
    const float* att_dst = (const float*)d_in[4];
    const float* bias    = (const float*)d_in[5];

    int N = in_sizes[0] / F_IN;
    int E = in_sizes[1] / 2;
    int n_check = E > 64 ? 64 : E;

    int EP = E + 3 * N + 64;
    if (EP > MAXE) EP = MAXE;
    int initT = EP;
    if (K2N * HC > initT) initT = K2N * HC;
    if (N + 1 > initT) initT = N + 1;

    // (1) init
    init_kernel<<<(initT + 255) / 256, 256>>>((const int*)ei, n_check, W, N, EP);

    // (2) gemm on side stream — overlaps the CSR build below
    cudaEventRecord(g_hx.evFork, 0);
    cudaStreamWaitEvent(g_hx.s2, g_hx.evFork, 0);
    gemm_alpha_kernel<<<(N + ROWS - 1) / ROWS, 256, 0, g_hx.s2>>>(x, att_src, att_dst, N);
    cudaEventRecord(g_hx.evJoin, g_hx.s2);

    // (3) fused persistent CSR build (count -> scan -> scatter, software grid barrier)
    csr_build_kernel<<<CSRB, 256>>>(ei, E, N);

    // (4) aggregate (joins gemm) — slot-4 kernel for ncu capture
    cudaStreamWaitEvent(0, g_hx.evJoin, 0);
    agg_kernel<<<(N + 7) / 8, 256>>>(bias, (float*)d_out, N);
}

// round 10
// speedup vs baseline: 1.0628x; 1.0628x over previous
#include <cuda_runtime.h>
#include <cuda_fp16.h>
#include <math_constants.h>
#include <cstdint>

#define F_IN 116
#define K2N  58          // F_IN/2
#define H 8
#define C 32
#define HC 256           // H*C
#define MAXN 50016
#define MAXE 1000000     // >= E + 3N + pad
#define NEG_SLOPE 0.2f
#define ROWS 32          // gemm rows per block
#define XSP 120          // padded shared row (16B multiple)
#define SCHUNK 2048      // scan chunk per block

// ---------------- device scratch (no allocations allowed) ----------------
__device__ __align__(16) __half g_xt_h[(size_t)MAXN * HC]; // fp16 features; row N stays 0 (sentinel)
__device__ __align__(16) float g_as[(size_t)MAXN * H];     // alpha_src (row N = -inf sentinel)
__device__ __align__(16) float g_ad[(size_t)MAXN * H];     // alpha_dst
__device__ unsigned long long g_Wt[K2N * HC];              // W repacked into k-pairs (f32x2)
__device__ __align__(16) int g_deg[MAXN];
__device__ int g_off[MAXN + 1];                            // aligned (ceil4) offsets
__device__ int g_cur[MAXN];
__device__ __align__(16) int g_csr[MAXE];                  // src ids grouped by dst, pad slots = N
__device__ int g_idx64;

// ---------------- side stream + events, created once at program start ----------------
struct HxStreams {
    cudaStream_t s2;
    cudaEvent_t evFork, evJoin;
    HxStreams() {
        cudaStreamCreateWithFlags(&s2, cudaStreamNonBlocking);
        cudaEventCreateWithFlags(&evFork, cudaEventDisableTiming);
        cudaEventCreateWithFlags(&evJoin, cudaEventDisableTiming);
    }
};
static HxStreams g_hx;

// ---------------- init: detect + zero deg + sentinel alpha row + W repack ----------------
__global__ void init_kernel(const int* ei32, int n_check, const float* __restrict__ W, int N) {
    int i = blockIdx.x * blockDim.x + threadIdx.x;
    if (i == 0) {
        int is64 = 1;
        for (int k = 0; k < n_check; k++)
            if (ei32[2 * k + 1] != 0) { is64 = 0; break; }
        g_idx64 = is64;
    }
    if (i < N) g_deg[i] = 0;
    if (i == N) {
#pragma unroll
        for (int h = 0; h < H; h++) g_as[(size_t)N * H + h] = -CUDART_INF_F;
    }
    if (i < K2N * HC) {
        int k2 = i / HC, j = i - k2 * HC;
        unsigned int lo = __float_as_uint(W[(2 * k2) * HC + j]);
        unsigned int hi = __float_as_uint(W[(2 * k2 + 1) * HC + j]);
        g_Wt[i] = ((unsigned long long)hi << 32) | lo;
    }
}

// ---------------- count in-degrees (dst half only) ----------------
__global__ void count_kernel(const void* __restrict__ ei, int E) {
    int i = blockIdx.x * blockDim.x + threadIdx.x;
    if (i >= E) return;
    int dst;
    if (g_idx64) dst = (int)((const long long*)ei)[(size_t)E + i];
    else         dst = ((const int*)ei)[E + i];
    atomicAdd(&g_deg[dst], 1);
}

// ---------------- single-kernel exclusive scan of ceil4(deg) -> g_off, g_cur ----------------
// Also writes the <=3 sentinel pad entries per node directly into g_csr.
__device__ __forceinline__ int ceil4(int v) { return (v + 3) & ~3; }

__global__ void scan_kernel(int N) {
    __shared__ int sm[256];
    int b0 = blockIdx.x * SCHUNK;                // multiple of 2048 -> int4-aligned
    int t = threadIdx.x;

    int base_p = 0;
    for (int i = t * 4; i < b0; i += 1024) {
        int4 d = *(const int4*)&g_deg[i];
        base_p += ceil4(d.x) + ceil4(d.y) + ceil4(d.z) + ceil4(d.w);
    }
    sm[t] = base_p;
    __syncthreads();
    for (int o = 128; o > 0; o >>= 1) {
        if (t < o) sm[t] += sm[t + o];
        __syncthreads();
    }
    int base = sm[0];
    __syncthreads();

    const int PT = SCHUNK / 256;
    int cbase = b0 + t * PT;
    int loc[PT];
    int s = 0;
#pragma unroll
    for (int k = 0; k < PT; k++) {
        int i = cbase + k;
        loc[k] = s;
        if (i < N) s += ceil4(g_deg[i]);
    }
    sm[t] = s;
    __syncthreads();
    for (int o = 1; o < 256; o <<= 1) {
        int v = (t >= o) ? sm[t - o] : 0;
        __syncthreads();
        sm[t] += v;
        __syncthreads();
    }
    int tbase = base + ((t > 0) ? sm[t - 1] : 0);
#pragma unroll
    for (int k = 0; k < PT; k++) {
        int i = cbase + k;
        if (i < N) {
            int o = tbase + loc[k];
            g_off[i] = o;
            g_cur[i] = o;
            int d = g_deg[i];
            int c4 = ceil4(d);
            for (int q = d; q < c4; q++) g_csr[o + q] = N;   // pad sentinels
        }
    }
    if (blockIdx.x == gridDim.x - 1 && t == 255) g_off[N] = base + sm[255];
}

// ---------------- scatter src ids into CSR slots ----------------
__global__ void scatter_kernel(const void* __restrict__ ei, int E) {
    int i = blockIdx.x * blockDim.x + threadIdx.x;
    if (i >= E) return;
    int src, dst;
    if (g_idx64) {
        const long long* p = (const long long*)ei;
        src = (int)p[i];
        dst = (int)p[(size_t)E + i];
    } else {
        const int* p = (const int*)ei;
        src = p[i];
        dst = p[E + i];
    }
    int pos = atomicAdd(&g_cur[dst], 1);
    g_csr[pos] = src;
}

// ---------------- xt = x @ W (f32x2 FFMA2, LDS.128) + alpha_src/alpha_dst ----------------
__global__ void __launch_bounds__(256, 2)
gemm_alpha_kernel(const float* __restrict__ x,
                  const float* __restrict__ att_src,
                  const float* __restrict__ att_dst,
                  int N) {
    __shared__ __align__(16) float xs[ROWS][XSP];
    int row0 = blockIdx.x * ROWS;

    for (int i = threadIdx.x; i < ROWS * F_IN; i += 256) {
        int r = i / F_IN, k = i - r * F_IN;
        int gr = row0 + r;
        xs[r][k] = (gr < N) ? x[(size_t)gr * F_IN + k] : 0.0f;
    }
    __syncthreads();

    int j = threadIdx.x;
    unsigned long long acc[ROWS];
#pragma unroll
    for (int r = 0; r < ROWS; r++) acc[r] = 0ull;

    const unsigned long long* wt = g_Wt + j;
    for (int k4 = 0; k4 < K2N / 2; k4++) {
        unsigned long long w0 = wt[(2 * k4) * HC];
        unsigned long long w1 = wt[(2 * k4 + 1) * HC];
#pragma unroll
        for (int r = 0; r < ROWS; r++) {
            ulonglong2 a2 = *(const ulonglong2*)&xs[r][4 * k4];
            asm("fma.rn.f32x2 %0, %1, %2, %0;" : "+l"(acc[r]) : "l"(a2.x), "l"(w0));
            asm("fma.rn.f32x2 %0, %1, %2, %0;" : "+l"(acc[r]) : "l"(a2.y), "l"(w1));
        }
    }

    float asv = att_src[j];
    float adv = att_dst[j];
    int h = j >> 5;

#pragma unroll
    for (int r = 0; r < ROWS; r++) {
        float lo, hi;
        asm("mov.b64 {%0, %1}, %2;" : "=f"(lo), "=f"(hi) : "l"(acc[r]));
        float v = lo + hi;
        int gr = row0 + r;
        if (gr < N) g_xt_h[(size_t)gr * HC + j] = __float2half_rn(v);
        float ps = v * asv;
        float pd = v * adv;
#pragma unroll
        for (int o = 16; o > 0; o >>= 1) {
            ps += __shfl_xor_sync(0xffffffffu, ps, o);
            pd += __shfl_xor_sync(0xffffffffu, pd, o);
        }
        if ((j & 31) == 0 && gr < N) {
            g_as[(size_t)gr * H + h] = ps;
            g_ad[(size_t)gr * H + h] = pd;
        }
    }
}

// ---------------- fused gather-aggregate + softmax + head-mean + bias + relu ----------------
__device__ __forceinline__ void acc_row(const float4& raw, float ev, float* acc) {
    const __half2* hp = (const __half2*)&raw;
    float2 f0 = __half22float2(hp[0]);
    float2 f1 = __half22float2(hp[1]);
    float2 f2 = __half22float2(hp[2]);
    float2 f3 = __half22float2(hp[3]);
    acc[0] = fmaf(ev, f0.x, acc[0]); acc[1] = fmaf(ev, f0.y, acc[1]);
    acc[2] = fmaf(ev, f1.x, acc[2]); acc[3] = fmaf(ev, f1.y, acc[3]);
    acc[4] = fmaf(ev, f2.x, acc[4]); acc[5] = fmaf(ev, f2.y, acc[5]);
    acc[6] = fmaf(ev, f3.x, acc[6]); acc[7] = fmaf(ev, f3.y, acc[7]);
}

__global__ void agg_kernel(const float* __restrict__ bias,
                           float* __restrict__ out, int N) {
    int gw = (blockIdx.x * blockDim.x + threadIdx.x) >> 5;
    int lane = threadIdx.x & 31;
    if (gw >= N) return;
    int n = gw;
    int h = lane >> 2;

    const char* asb = (const char*)g_as;     // 32-bit byte-offset addressing
    const char* xtb = (const char*)g_xt_h;
    int hoff = h << 2;                       // h * 4 bytes
    int loff = lane << 4;                    // lane * 16 bytes

    float ad_h = *(const float*)(asb + (((unsigned)n << 5) + hoff) + (unsigned)((char*)g_ad - (char*)g_as));

    // self loop
    float a = *(const float*)(asb + (((unsigned)n << 5) + hoff)) + ad_h;
    a = (a > 0.0f) ? a : NEG_SLOPE * a;
    float e = __expf(a);
    float s = e;

    float acc[8] = {0, 0, 0, 0, 0, 0, 0, 0};
    {
        float4 raw = *(const float4*)(xtb + ((unsigned)n << 9) + loff);
        acc_row(raw, e, acc);
    }

    int beg = g_off[n];
    int end = g_off[n + 1];     // ceil4-aligned; padding = sentinel entries (exp=0, zero row)
    for (int p = beg; p < end; p += 4) {
        int4 sv = *(const int4*)(g_csr + p);
        float a0 = *(const float*)(asb + (((unsigned)sv.x << 5) + hoff)) + ad_h;
        float a1 = *(const float*)(asb + (((unsigned)sv.y << 5) + hoff)) + ad_h;
        float a2 = *(const float*)(asb + (((unsigned)sv.z << 5) + hoff)) + ad_h;
        float a3 = *(const float*)(asb + (((unsigned)sv.w << 5) + hoff)) + ad_h;
        a0 = (a0 > 0.0f) ? a0 : NEG_SLOPE * a0;
        a1 = (a1 > 0.0f) ? a1 : NEG_SLOPE * a1;
        a2 = (a2 > 0.0f) ? a2 : NEG_SLOPE * a2;
        a3 = (a3 > 0.0f) ? a3 : NEG_SLOPE * a3;
        float e0 = __expf(a0);
        float e1 = __expf(a1);
        float e2 = __expf(a2);
        float e3 = __expf(a3);
        s += (e0 + e1) + (e2 + e3);
        float4 r0 = *(const float4*)(xtb + ((unsigned)sv.x << 9) + loff);
        float4 r1 = *(const float4*)(xtb + ((unsigned)sv.y << 9) + loff);
        float4 r2 = *(const float4*)(xtb + ((unsigned)sv.z << 9) + loff);
        float4 r3 = *(const float4*)(xtb + ((unsigned)sv.w << 9) + loff);
        acc_row(r0, e0, acc);
        acc_row(r1, e1, acc);
        acc_row(r2, e2, acc);
        acc_row(r3, e3, acc);
    }

    float inv = 1.0f / (s + 1e-16f);
    float r[8];
#pragma unroll
    for (int i = 0; i < 8; i++) r[i] = acc[i] * inv;

    // sum over heads: butterfly across lanes differing in bits 2..4 (same lane&3)
#pragma unroll
    for (int i = 0; i < 8; i++) {
        r[i] += __shfl_xor_sync(0xffffffffu, r[i], 4);
        r[i] += __shfl_xor_sync(0xffffffffu, r[i], 8);
        r[i] += __shfl_xor_sync(0xffffffffu, r[i], 16);
    }

    if (lane < 4) {
        float o[8];
#pragma unroll
        for (int i = 0; i < 8; i++) {
            float v = r[i] * 0.125f + bias[lane * 8 + i];
            o[i] = (v > 0.0f) ? v : 0.0f;
        }
        float4* orow = (float4*)(out + (size_t)n * C + lane * 8);
        orow[0] = make_float4(o[0], o[1], o[2], o[3]);
        orow[1] = make_float4(o[4], o[5], o[6], o[7]);
    }
}

// ---------------- launch: init, count, scan, gemm(slot4, s2), scatter, agg ----------------
extern "C" void kernel_launch(void* const* d_in, const int* in_sizes, int n_in,
                              void* d_out, int out_size) {
    const float* x       = (const float*)d_in[0];
    const void*  ei      = d_in[1];
    const float* W       = (const float*)d_in[2];
    const float* att_src = (const float*)d_in[3];
    const float* att_dst = (const float*)d_in[4];
    const float* bias    = (const float*)d_in[5];

    int N = in_sizes[0] / F_IN;
    int E = in_sizes[1] / 2;
    int n_check = E > 64 ? 64 : E;

    int initT = K2N * HC;
    if (N + 1 > initT) initT = N + 1;

    // (1) init
    init_kernel<<<(initT + 255) / 256, 256>>>((const int*)ei, n_check, W, N);
    cudaEventRecord(g_hx.evFork, 0);

    // (2) count, (3) scan  [main stream]
    count_kernel<<<(E + 255) / 256, 256>>>(ei, E);
    int NB = (N + SCHUNK - 1) / SCHUNK;
    scan_kernel<<<NB, 256>>>(N);

    // (4) gemm on side stream — profile slot 4; overlaps count/scan/scatter
    cudaStreamWaitEvent(g_hx.s2, g_hx.evFork, 0);
    gemm_alpha_kernel<<<(N + ROWS - 1) / ROWS, 256, 0, g_hx.s2>>>(x, att_src, att_dst, N);
    cudaEventRecord(g_hx.evJoin, g_hx.s2);

    // (5) scatter [main stream]
    scatter_kernel<<<(E + 255) / 256, 256>>>(ei, E);

    // (6) aggregate (joins gemm)
    cudaStreamWaitEvent(0, g_hx.evJoin, 0);
    agg_kernel<<<(N + 7) / 8, 256>>>(bias, (float*)d_out, N);
}

// round 11
// speedup vs baseline: 1.0976x; 1.0328x over previous
#include <cuda_runtime.h>
#include <cuda_fp16.h>
#include <math_constants.h>
#include <cstdint>

#define F_IN 116
#define K2N  58          // real k-pairs (F_IN/2)
#define K4P  64          // padded k-pairs (zeros beyond 58)
#define NCH  8           // weight chunks
#define KPC  8           // k-pairs per chunk
#define H 8
#define C 32
#define HC 256           // H*C
#define MAXN 50016
#define MAXE 1000000
#define NEG_SLOPE 0.2f
#define ROWS 16          // gemm rows per block
#define XSW 128          // xs width in floats (padded, 16B multiple)
#define SCHUNK 2048      // scan chunk per block

// ---------------- device scratch (no allocations allowed) ----------------
__device__ __align__(16) __half g_xt_h[(size_t)MAXN * HC]; // fp16 features; row N stays 0 (sentinel)
__device__ __align__(16) float g_as[(size_t)MAXN * H];     // alpha_src (row N = -inf sentinel)
__device__ __align__(16) float g_ad[(size_t)MAXN * H];     // alpha_dst
__device__ __align__(16) unsigned long long g_Wt[K4P * HC];// W repacked into k-pairs (f32x2), zero-padded
__device__ __align__(16) int g_deg[MAXN];
__device__ int g_off[MAXN + 1];                            // aligned (ceil4) offsets
__device__ int g_cur[MAXN];
__device__ __align__(16) int g_csr[MAXE];                  // src ids grouped by dst, pad slots = N
__device__ int g_idx64;

// ---------------- side stream + events, created once at program start ----------------
struct HxStreams {
    cudaStream_t s2;
    cudaEvent_t evFork, evJoin;
    HxStreams() {
        cudaStreamCreateWithFlags(&s2, cudaStreamNonBlocking);
        cudaEventCreateWithFlags(&evFork, cudaEventDisableTiming);
        cudaEventCreateWithFlags(&evJoin, cudaEventDisableTiming);
    }
};
static HxStreams g_hx;

// ---------------- init: detect + zero deg + sentinel alpha row + padded W repack ----------------
__global__ void init_kernel(const int* ei32, int n_check, const float* __restrict__ W, int N) {
    int i = blockIdx.x * blockDim.x + threadIdx.x;
    if (i == 0) {
        int is64 = 1;
        for (int k = 0; k < n_check; k++)
            if (ei32[2 * k + 1] != 0) { is64 = 0; break; }
        g_idx64 = is64;
    }
    if (i < N) g_deg[i] = 0;
    if (i == N) {
#pragma unroll
        for (int h = 0; h < H; h++) g_as[(size_t)N * H + h] = -CUDART_INF_F;
    }
    if (i < K4P * HC) {
        int k2 = i >> 8, j = i & 255;
        unsigned long long v = 0ull;
        if (k2 < K2N) {
            unsigned int lo = __float_as_uint(W[(2 * k2) * HC + j]);
            unsigned int hi = __float_as_uint(W[(2 * k2 + 1) * HC + j]);
            v = ((unsigned long long)hi << 32) | lo;
        }
        g_Wt[i] = v;
    }
}

// ---------------- count in-degrees (dst half only) ----------------
__global__ void count_kernel(const void* __restrict__ ei, int E) {
    int i = blockIdx.x * blockDim.x + threadIdx.x;
    if (i >= E) return;
    int dst;
    if (g_idx64) dst = (int)((const long long*)ei)[(size_t)E + i];
    else         dst = ((const int*)ei)[E + i];
    atomicAdd(&g_deg[dst], 1);
}

// ---------------- single-kernel exclusive scan of ceil4(deg) -> g_off, g_cur ----------------
__device__ __forceinline__ int ceil4(int v) { return (v + 3) & ~3; }

__global__ void scan_kernel(int N) {
    __shared__ int sm[256];
    int b0 = blockIdx.x * SCHUNK;
    int t = threadIdx.x;

    int base_p = 0;
    for (int i = t * 4; i < b0; i += 1024) {
        int4 d = *(const int4*)&g_deg[i];
        base_p += ceil4(d.x) + ceil4(d.y) + ceil4(d.z) + ceil4(d.w);
    }
    sm[t] = base_p;
    __syncthreads();
    for (int o = 128; o > 0; o >>= 1) {
        if (t < o) sm[t] += sm[t + o];
        __syncthreads();
    }
    int base = sm[0];
    __syncthreads();

    const int PT = SCHUNK / 256;
    int cbase = b0 + t * PT;
    int loc[PT];
    int s = 0;
#pragma unroll
    for (int k = 0; k < PT; k++) {
        int i = cbase + k;
        loc[k] = s;
        if (i < N) s += ceil4(g_deg[i]);
    }
    sm[t] = s;
    __syncthreads();
    for (int o = 1; o < 256; o <<= 1) {
        int v = (t >= o) ? sm[t - o] : 0;
        __syncthreads();
        sm[t] += v;
        __syncthreads();
    }
    int tbase = base + ((t > 0) ? sm[t - 1] : 0);
#pragma unroll
    for (int k = 0; k < PT; k++) {
        int i = cbase + k;
        if (i < N) {
            int o = tbase + loc[k];
            g_off[i] = o;
            g_cur[i] = o;
            int d = g_deg[i];
            int c4 = ceil4(d);
            for (int q = d; q < c4; q++) g_csr[o + q] = N;   // pad sentinels
        }
    }
    if (blockIdx.x == gridDim.x - 1 && t == 255) g_off[N] = base + sm[255];
}

// ---------------- scatter src ids into CSR slots ----------------
__global__ void scatter_kernel(const void* __restrict__ ei, int E) {
    int i = blockIdx.x * blockDim.x + threadIdx.x;
    if (i >= E) return;
    int src, dst;
    if (g_idx64) {
        const long long* p = (const long long*)ei;
        src = (int)p[i];
        dst = (int)p[(size_t)E + i];
    } else {
        const int* p = (const int*)ei;
        src = p[i];
        dst = p[E + i];
    }
    int pos = atomicAdd(&g_cur[dst], 1);
    g_csr[pos] = src;
}

// ---------------- xt = x @ W: cp.async double-buffered weights + f32x2 FFMA2 ----------------
__global__ void __launch_bounds__(256, 3)
gemm_alpha_kernel(const float* __restrict__ x,
                  const float* __restrict__ att_src,
                  const float* __restrict__ att_dst,
                  int N) {
    __shared__ __align__(16) float xs[ROWS][XSW];
    __shared__ __align__(16) unsigned long long wbuf[2][KPC][HC];
    int t = threadIdx.x;
    int row0 = blockIdx.x * ROWS;

    // prefetch weight chunk 0 (cp.async, 16B granules: 1024 uint4 over 256 threads)
    {
        const uint4* s4 = (const uint4*)g_Wt;
#pragma unroll
        for (int q = 0; q < 4; q++) {
            uint32_t sa = (uint32_t)__cvta_generic_to_shared(&((uint4*)&wbuf[0][0][0])[q * 256 + t]);
            asm volatile("cp.async.cg.shared.global [%0], [%1], 16;" :: "r"(sa), "l"(s4 + q * 256 + t));
        }
        asm volatile("cp.async.commit_group;");
    }

    // fill x tile (zero-padded to 128 cols)
    for (int i = t; i < ROWS * XSW; i += 256) {
        int r = i >> 7, k = i & 127;
        int gr = row0 + r;
        xs[r][k] = (k < F_IN && gr < N) ? x[(size_t)gr * F_IN + k] : 0.0f;
    }

    unsigned long long acc[ROWS];
#pragma unroll
    for (int r = 0; r < ROWS; r++) acc[r] = 0ull;

#pragma unroll 1
    for (int c = 0; c < NCH; c++) {
        if (c + 1 < NCH) {
            const uint4* s4 = (const uint4*)(g_Wt + (size_t)(c + 1) * KPC * HC);
            uint4* dst = (uint4*)&wbuf[(c + 1) & 1][0][0];
#pragma unroll
            for (int q = 0; q < 4; q++) {
                uint32_t sa = (uint32_t)__cvta_generic_to_shared(dst + q * 256 + t);
                asm volatile("cp.async.cg.shared.global [%0], [%1], 16;" :: "r"(sa), "l"(s4 + q * 256 + t));
            }
            asm volatile("cp.async.commit_group;");
            asm volatile("cp.async.wait_group 1;");
        } else {
            asm volatile("cp.async.wait_group 0;");
        }
        __syncthreads();

        int b = c & 1;
#pragma unroll
        for (int kk4 = 0; kk4 < KPC / 2; kk4++) {
            unsigned long long w0 = wbuf[b][2 * kk4][t];
            unsigned long long w1 = wbuf[b][2 * kk4 + 1][t];
#pragma unroll
            for (int r = 0; r < ROWS; r++) {
                ulonglong2 a2 = *(const ulonglong2*)&xs[r][c * 16 + kk4 * 4];
                asm("fma.rn.f32x2 %0, %1, %2, %0;" : "+l"(acc[r]) : "l"(a2.x), "l"(w0));
                asm("fma.rn.f32x2 %0, %1, %2, %0;" : "+l"(acc[r]) : "l"(a2.y), "l"(w1));
            }
        }
        __syncthreads();
    }

    float asv = att_src[t];
    float adv = att_dst[t];
    int h = t >> 5;

#pragma unroll
    for (int r = 0; r < ROWS; r++) {
        float lo, hi;
        asm("mov.b64 {%0, %1}, %2;" : "=f"(lo), "=f"(hi) : "l"(acc[r]));
        float v = lo + hi;
        int gr = row0 + r;
        if (gr < N) g_xt_h[(size_t)gr * HC + t] = __float2half_rn(v);
        float ps = v * asv;
        float pd = v * adv;
#pragma unroll
        for (int o = 16; o > 0; o >>= 1) {
            ps += __shfl_xor_sync(0xffffffffu, ps, o);
            pd += __shfl_xor_sync(0xffffffffu, pd, o);
        }
        if ((t & 31) == 0 && gr < N) {
            g_as[(size_t)gr * H + h] = ps;
            g_ad[(size_t)gr * H + h] = pd;
        }
    }
}

// ---------------- fused gather-aggregate + softmax + head-mean + bias + relu ----------------
__device__ __forceinline__ void acc_row(const float4& raw, float ev, float* acc) {
    const __half2* hp = (const __half2*)&raw;
    float2 f0 = __half22float2(hp[0]);
    float2 f1 = __half22float2(hp[1]);
    float2 f2 = __half22float2(hp[2]);
    float2 f3 = __half22float2(hp[3]);
    acc[0] = fmaf(ev, f0.x, acc[0]); acc[1] = fmaf(ev, f0.y, acc[1]);
    acc[2] = fmaf(ev, f1.x, acc[2]); acc[3] = fmaf(ev, f1.y, acc[3]);
    acc[4] = fmaf(ev, f2.x, acc[4]); acc[5] = fmaf(ev, f2.y, acc[5]);
    acc[6] = fmaf(ev, f3.x, acc[6]); acc[7] = fmaf(ev, f3.y, acc[7]);
}

__global__ void agg_kernel(const float* __restrict__ bias,
                           float* __restrict__ out, int N) {
    int gw = (blockIdx.x * blockDim.x + threadIdx.x) >> 5;
    int lane = threadIdx.x & 31;
    if (gw >= N) return;
    int n = gw;
    int h = lane >> 2;

    const char* asb = (const char*)g_as;
    const char* xtb = (const char*)g_xt_h;
    int hoff = h << 2;
    int loff = lane << 4;

    float ad_h = g_ad[(size_t)n * H + h];

    // self loop
    float a = *(const float*)(asb + (((unsigned)n << 5) + hoff)) + ad_h;
    a = (a > 0.0f) ? a : NEG_SLOPE * a;
    float e = __expf(a);
    float s = e;

    float acc[8] = {0, 0, 0, 0, 0, 0, 0, 0};
    {
        float4 raw = *(const float4*)(xtb + ((unsigned)n << 9) + loff);
        acc_row(raw, e, acc);
    }

    int beg = g_off[n];
    int end = g_off[n + 1];
    for (int p = beg; p < end; p += 4) {
        int4 sv = *(const int4*)(g_csr + p);
        float a0 = *(const float*)(asb + (((unsigned)sv.x << 5) + hoff)) + ad_h;
        float a1 = *(const float*)(asb + (((unsigned)sv.y << 5) + hoff)) + ad_h;
        float a2 = *(const float*)(asb + (((unsigned)sv.z << 5) + hoff)) + ad_h;
        float a3 = *(const float*)(asb + (((unsigned)sv.w << 5) + hoff)) + ad_h;
        a0 = (a0 > 0.0f) ? a0 : NEG_SLOPE * a0;
        a1 = (a1 > 0.0f) ? a1 : NEG_SLOPE * a1;
        a2 = (a2 > 0.0f) ? a2 : NEG_SLOPE * a2;
        a3 = (a3 > 0.0f) ? a3 : NEG_SLOPE * a3;
        float e0 = __expf(a0);
        float e1 = __expf(a1);
        float e2 = __expf(a2);
        float e3 = __expf(a3);
        s += (e0 + e1) + (e2 + e3);
        float4 r0 = *(const float4*)(xtb + ((unsigned)sv.x << 9) + loff);
        float4 r1 = *(const float4*)(xtb + ((unsigned)sv.y << 9) + loff);
        float4 r2 = *(const float4*)(xtb + ((unsigned)sv.z << 9) + loff);
        float4 r3 = *(const float4*)(xtb + ((unsigned)sv.w << 9) + loff);
        acc_row(r0, e0, acc);
        acc_row(r1, e1, acc);
        acc_row(r2, e2, acc);
        acc_row(r3, e3, acc);
    }

    float inv = 1.0f / (s + 1e-16f);
    float r[8];
#pragma unroll
    for (int i = 0; i < 8; i++) r[i] = acc[i] * inv;

#pragma unroll
    for (int i = 0; i < 8; i++) {
        r[i] += __shfl_xor_sync(0xffffffffu, r[i], 4);
        r[i] += __shfl_xor_sync(0xffffffffu, r[i], 8);
        r[i] += __shfl_xor_sync(0xffffffffu, r[i], 16);
    }

    if (lane < 4) {
        float o[8];
#pragma unroll
        for (int i = 0; i < 8; i++) {
            float v = r[i] * 0.125f + bias[lane * 8 + i];
            o[i] = (v > 0.0f) ? v : 0.0f;
        }
        float4* orow = (float4*)(out + (size_t)n * C + lane * 8);
        orow[0] = make_float4(o[0], o[1], o[2], o[3]);
        orow[1] = make_float4(o[4], o[5], o[6], o[7]);
    }
}

// ---------------- launch: init, count, scan, gemm(slot4, s2), scatter, agg ----------------
extern "C" void kernel_launch(void* const* d_in, const int* in_sizes, int n_in,
                              void* d_out, int out_size) {
    const float* x       = (const float*)d_in[0];
    const void*  ei      = d_in[1];
    const float* W       = (const float*)d_in[2];
    const float* att_src = (const float*)d_in[3];
    const float* att_dst = (const float*)d_in[4];
    const float* bias    = (const float*)d_in[5];

    int N = in_sizes[0] / F_IN;
    int E = in_sizes[1] / 2;
    int n_check = E > 64 ? 64 : E;

    int initT = K4P * HC;
    if (N + 1 > initT) initT = N + 1;

    // (1) init
    init_kernel<<<(initT + 255) / 256, 256>>>((const int*)ei, n_check, W, N);
    cudaEventRecord(g_hx.evFork, 0);

    // (2) count, (3) scan  [main stream]
    count_kernel<<<(E + 255) / 256, 256>>>(ei, E);
    int NB = (N + SCHUNK - 1) / SCHUNK;
    scan_kernel<<<NB, 256>>>(N);

    // (4) gemm on side stream — profile slot 4; overlaps count/scan/scatter
    cudaStreamWaitEvent(g_hx.s2, g_hx.evFork, 0);
    gemm_alpha_kernel<<<(N + ROWS - 1) / ROWS, 256, 0, g_hx.s2>>>(x, att_src, att_dst, N);
    cudaEventRecord(g_hx.evJoin, g_hx.s2);

    // (5) scatter [main stream]
    scatter_kernel<<<(E + 255) / 256, 256>>>(ei, E);

    // (6) aggregate (joins gemm)
    cudaStreamWaitEvent(0, g_hx.evJoin, 0);
    agg_kernel<<<(N + 7) / 8, 256>>>(bias, (float*)d_out, N);
}

// round 12
// speedup vs baseline: 1.9172x; 1.7467x over previous
#include <cuda_runtime.h>
#include <cuda_fp16.h>
#include <cuda_bf16.h>
#include <math_constants.h>
#include <cstdint>

#define F_IN 116
#define H 8
#define C 32
#define HC 256           // H*C
#define MAXN 50016
#define MAXE 1000000
#define NEG_SLOPE 0.2f
#define MROWS 32         // gemm rows per block
#define XSW 132          // padded xs row (floats): 132%32=4 -> conflict-free, even
#define SCHUNK 2048      // scan chunk per block

// ---------------- device scratch (no allocations allowed) ----------------
__device__ __align__(16) __half g_xt_h[(size_t)MAXN * HC]; // fp16 features; row N stays 0 (sentinel)
__device__ __align__(16) float g_as[(size_t)MAXN * H];     // alpha_src (row N = -inf sentinel)
__device__ __align__(16) float g_ad[(size_t)MAXN * H];     // alpha_dst
__device__ __align__(16) uint2 g_Wb[2][8][32][32];         // W bf16 fragments [hi/lo][kstep][ntile][lane]
__device__ __align__(16) int g_deg[MAXN];
__device__ int g_off[MAXN + 1];                            // aligned (ceil4) offsets
__device__ int g_cur[MAXN];
__device__ __align__(16) int g_csr[MAXE];                  // src ids grouped by dst, pad slots = N
__device__ int g_idx64;

// ---------------- side stream + events ----------------
struct HxStreams {
    cudaStream_t s2;
    cudaEvent_t evFork, evJoin;
    HxStreams() {
        cudaStreamCreateWithFlags(&s2, cudaStreamNonBlocking);
        cudaEventCreateWithFlags(&evFork, cudaEventDisableTiming);
        cudaEventCreateWithFlags(&evJoin, cudaEventDisableTiming);
    }
};
static HxStreams g_hx;

// pack two floats to bf16x2: a -> low half, b -> high half
__device__ __forceinline__ uint32_t packbf(float a, float b) {
    uint32_t r;
    asm("cvt.rn.bf16x2.f32 %0, %1, %2;" : "=r"(r) : "f"(b), "f"(a));
    return r;
}
__device__ __forceinline__ float bf_lo_f(uint32_t u) { return __uint_as_float(u << 16); }
__device__ __forceinline__ float bf_hi_f(uint32_t u) { return __uint_as_float(u & 0xffff0000u); }

// ---------------- init: detect + zero deg + sentinel row + W bf16-split fragment pack ----------------
__global__ void init_kernel(const int* ei32, int n_check, const float* __restrict__ W, int N) {
    int i = blockIdx.x * blockDim.x + threadIdx.x;
    if (i == 0) {
        int is64 = 1;
        for (int k = 0; k < n_check; k++)
            if (ei32[2 * k + 1] != 0) { is64 = 0; break; }
        g_idx64 = is64;
    }
    if (i < N) g_deg[i] = 0;
    if (i == N) {
#pragma unroll
        for (int h = 0; h < H; h++) g_as[(size_t)N * H + h] = -CUDART_INF_F;
    }
    if (i < 8192) {      // 8 ksteps * 32 ntiles * 32 lanes
        int ks = i >> 10;
        int rem = i & 1023;
        int gnt = rem >> 5;
        int lane = rem & 31;
        int g = lane >> 2, tig = lane & 3;
        int n = gnt * 8 + g;
        int k0 = ks * 16 + tig * 2;
        float w00 = (k0     < F_IN) ? W[(k0)     * HC + n] : 0.0f;
        float w01 = (k0 + 1 < F_IN) ? W[(k0 + 1) * HC + n] : 0.0f;
        float w10 = (k0 + 8 < F_IN) ? W[(k0 + 8) * HC + n] : 0.0f;
        float w11 = (k0 + 9 < F_IN) ? W[(k0 + 9) * HC + n] : 0.0f;
        uint32_t h0 = packbf(w00, w01);
        uint32_t h1 = packbf(w10, w11);
        uint32_t l0 = packbf(w00 - bf_lo_f(h0), w01 - bf_hi_f(h0));
        uint32_t l1 = packbf(w10 - bf_lo_f(h1), w11 - bf_hi_f(h1));
        g_Wb[0][ks][gnt][lane] = make_uint2(h0, h1);
        g_Wb[1][ks][gnt][lane] = make_uint2(l0, l1);
    }
}

// ---------------- count in-degrees (dst half only) ----------------
__global__ void count_kernel(const void* __restrict__ ei, int E) {
    int i = blockIdx.x * blockDim.x + threadIdx.x;
    if (i >= E) return;
    int dst;
    if (g_idx64) dst = (int)((const long long*)ei)[(size_t)E + i];
    else         dst = ((const int*)ei)[E + i];
    atomicAdd(&g_deg[dst], 1);
}

// ---------------- single-kernel exclusive scan of ceil4(deg) -> g_off, g_cur ----------------
__device__ __forceinline__ int ceil4(int v) { return (v + 3) & ~3; }

__global__ void scan_kernel(int N) {
    __shared__ int sm[256];
    int b0 = blockIdx.x * SCHUNK;
    int t = threadIdx.x;

    int base_p = 0;
    for (int i = t * 4; i < b0; i += 1024) {
        int4 d = *(const int4*)&g_deg[i];
        base_p += ceil4(d.x) + ceil4(d.y) + ceil4(d.z) + ceil4(d.w);
    }
    sm[t] = base_p;
    __syncthreads();
    for (int o = 128; o > 0; o >>= 1) {
        if (t < o) sm[t] += sm[t + o];
        __syncthreads();
    }
    int base = sm[0];
    __syncthreads();

    const int PT = SCHUNK / 256;
    int cbase = b0 + t * PT;
    int loc[PT];
    int s = 0;
#pragma unroll
    for (int k = 0; k < PT; k++) {
        int i = cbase + k;
        loc[k] = s;
        if (i < N) s += ceil4(g_deg[i]);
    }
    sm[t] = s;
    __syncthreads();
    for (int o = 1; o < 256; o <<= 1) {
        int v = (t >= o) ? sm[t - o] : 0;
        __syncthreads();
        sm[t] += v;
        __syncthreads();
    }
    int tbase = base + ((t > 0) ? sm[t - 1] : 0);
#pragma unroll
    for (int k = 0; k < PT; k++) {
        int i = cbase + k;
        if (i < N) {
            int o = tbase + loc[k];
            g_off[i] = o;
            g_cur[i] = o;
            int d = g_deg[i];
            int c4 = ceil4(d);
            for (int q = d; q < c4; q++) g_csr[o + q] = N;
        }
    }
    if (blockIdx.x == gridDim.x - 1 && t == 255) g_off[N] = base + sm[255];
}

// ---------------- scatter src ids into CSR slots ----------------
__global__ void scatter_kernel(const void* __restrict__ ei, int E) {
    int i = blockIdx.x * blockDim.x + threadIdx.x;
    if (i >= E) return;
    int src, dst;
    if (g_idx64) {
        const long long* p = (const long long*)ei;
        src = (int)p[i];
        dst = (int)p[(size_t)E + i];
    } else {
        const int* p = (const int*)ei;
        src = p[i];
        dst = p[E + i];
    }
    int pos = atomicAdd(&g_cur[dst], 1);
    g_csr[pos] = src;
}

// ---------------- gemm: HMMA bf16 2-term split, fp32 accum + alphas ----------------
// Block: 256 thr = 8 warps as 2(m)x4(n); block tile 32 rows x 256 cols, K padded 128.
// Warp (mw, nw): rows mw*16..+15, cols nw*64..+63 (8 mma n-tiles), heads {2nw, 2nw+1}.
__device__ __forceinline__ void mma_bf16(float* d, uint32_t a0, uint32_t a1, uint32_t a2, uint32_t a3,
                                         uint32_t b0, uint32_t b1) {
    asm("mma.sync.aligned.m16n8k16.row.col.f32.bf16.bf16.f32 "
        "{%0,%1,%2,%3}, {%4,%5,%6,%7}, {%8,%9}, {%0,%1,%2,%3};"
        : "+f"(d[0]), "+f"(d[1]), "+f"(d[2]), "+f"(d[3])
        : "r"(a0), "r"(a1), "r"(a2), "r"(a3), "r"(b0), "r"(b1));
}

__global__ void __launch_bounds__(256, 3)
gemm_alpha_kernel(const float* __restrict__ x,
                  const float* __restrict__ att_src,
                  const float* __restrict__ att_dst,
                  int N) {
    __shared__ __align__(16) float xs[MROWS][XSW];
    int t = threadIdx.x;
    int w = t >> 5, lane = t & 31;
    int g = lane >> 2, tig = lane & 3;
    int mw = w >> 2, nw = w & 3;
    int row0 = blockIdx.x * MROWS;

    // stage x tile (fp32, zero-padded to 128 cols)
    for (int i = t; i < MROWS * 128; i += 256) {
        int r = i >> 7, c = i & 127;
        int gr = row0 + r;
        xs[r][c] = (c < F_IN && gr < N) ? x[(size_t)gr * F_IN + c] : 0.0f;
    }
    __syncthreads();

    float d[8][4];
#pragma unroll
    for (int nt = 0; nt < 8; nt++)
#pragma unroll
        for (int q = 0; q < 4; q++) d[nt][q] = 0.0f;

    int ra = mw * 16 + g;
    int rb = ra + 8;

#pragma unroll
    for (int ks = 0; ks < 8; ks++) {
        int k0 = ks * 16 + tig * 2;
        float2 xa = *(const float2*)&xs[ra][k0];
        float2 xb = *(const float2*)&xs[rb][k0];
        float2 xc = *(const float2*)&xs[ra][k0 + 8];
        float2 xd = *(const float2*)&xs[rb][k0 + 8];
        uint32_t ah0 = packbf(xa.x, xa.y);
        uint32_t ah1 = packbf(xb.x, xb.y);
        uint32_t ah2 = packbf(xc.x, xc.y);
        uint32_t ah3 = packbf(xd.x, xd.y);
        uint32_t al0 = packbf(xa.x - bf_lo_f(ah0), xa.y - bf_hi_f(ah0));
        uint32_t al1 = packbf(xb.x - bf_lo_f(ah1), xb.y - bf_hi_f(ah1));
        uint32_t al2 = packbf(xc.x - bf_lo_f(ah2), xc.y - bf_hi_f(ah2));
        uint32_t al3 = packbf(xd.x - bf_lo_f(ah3), xd.y - bf_hi_f(ah3));

#pragma unroll
        for (int nt = 0; nt < 8; nt++) {
            int gnt = nw * 8 + nt;
            uint2 bh = g_Wb[0][ks][gnt][lane];
            uint2 bl = g_Wb[1][ks][gnt][lane];
            mma_bf16(d[nt], ah0, ah1, ah2, ah3, bh.x, bh.y);
            mma_bf16(d[nt], ah0, ah1, ah2, ah3, bl.x, bl.y);
            mma_bf16(d[nt], al0, al1, al2, al3, bh.x, bh.y);
        }
    }

    // epilogue: store fp16 xt + per-(row, head) alpha partials
    int gr0 = row0 + ra;
    int gr1 = row0 + rb;
    float pS[2][2] = {{0, 0}, {0, 0}};   // [rowsel][headsel]
    float pD[2][2] = {{0, 0}, {0, 0}};
    __half2* xt2 = (__half2*)g_xt_h;

#pragma unroll
    for (int nt = 0; nt < 8; nt++) {
        int col = nw * 64 + nt * 8 + tig * 2;
        int hs = nt >> 2;
        float s0 = __ldg(&att_src[col]);
        float s1 = __ldg(&att_src[col + 1]);
        float t0 = __ldg(&att_dst[col]);
        float t1 = __ldg(&att_dst[col + 1]);
        pS[0][hs] += d[nt][0] * s0 + d[nt][1] * s1;
        pS[1][hs] += d[nt][2] * s0 + d[nt][3] * s1;
        pD[0][hs] += d[nt][0] * t0 + d[nt][1] * t1;
        pD[1][hs] += d[nt][2] * t0 + d[nt][3] * t1;
        if (gr0 < N) xt2[(size_t)gr0 * 128 + (col >> 1)] = __floats2half2_rn(d[nt][0], d[nt][1]);
        if (gr1 < N) xt2[(size_t)gr1 * 128 + (col >> 1)] = __floats2half2_rn(d[nt][2], d[nt][3]);
    }

    // butterfly over tig (lane bits 0,1) -> full 32-col head sums
#pragma unroll
    for (int rs = 0; rs < 2; rs++)
#pragma unroll
        for (int hsl = 0; hsl < 2; hsl++) {
            float v1 = pS[rs][hsl];
            v1 += __shfl_xor_sync(0xffffffffu, v1, 1);
            v1 += __shfl_xor_sync(0xffffffffu, v1, 2);
            pS[rs][hsl] = v1;
            float v2 = pD[rs][hsl];
            v2 += __shfl_xor_sync(0xffffffffu, v2, 1);
            v2 += __shfl_xor_sync(0xffffffffu, v2, 2);
            pD[rs][hsl] = v2;
        }

    if (tig == 0) {
#pragma unroll
        for (int rs = 0; rs < 2; rs++) {
            int gr = (rs == 0) ? gr0 : gr1;
            if (gr < N) {
#pragma unroll
                for (int hsl = 0; hsl < 2; hsl++) {
                    int h = nw * 2 + hsl;
                    g_as[(size_t)gr * H + h] = pS[rs][hsl];
                    g_ad[(size_t)gr * H + h] = pD[rs][hsl];
                }
            }
        }
    }
}

// ---------------- fused gather-aggregate + softmax + head-mean + bias + relu ----------------
__device__ __forceinline__ void acc_row(const float4& raw, float ev, float* acc) {
    const __half2* hp = (const __half2*)&raw;
    float2 f0 = __half22float2(hp[0]);
    float2 f1 = __half22float2(hp[1]);
    float2 f2 = __half22float2(hp[2]);
    float2 f3 = __half22float2(hp[3]);
    acc[0] = fmaf(ev, f0.x, acc[0]); acc[1] = fmaf(ev, f0.y, acc[1]);
    acc[2] = fmaf(ev, f1.x, acc[2]); acc[3] = fmaf(ev, f1.y, acc[3]);
    acc[4] = fmaf(ev, f2.x, acc[4]); acc[5] = fmaf(ev, f2.y, acc[5]);
    acc[6] = fmaf(ev, f3.x, acc[6]); acc[7] = fmaf(ev, f3.y, acc[7]);
}

__global__ void agg_kernel(const float* __restrict__ bias,
                           float* __restrict__ out, int N) {
    int gw = (blockIdx.x * blockDim.x + threadIdx.x) >> 5;
    int lane = threadIdx.x & 31;
    if (gw >= N) return;
    int n = gw;
    int h = lane >> 2;

    const char* asb = (const char*)g_as;
    const char* xtb = (const char*)g_xt_h;
    int hoff = h << 2;
    int loff = lane << 4;

    float ad_h = g_ad[(size_t)n * H + h];

    float a = *(const float*)(asb + (((unsigned)n << 5) + hoff)) + ad_h;
    a = (a > 0.0f) ? a : NEG_SLOPE * a;
    float e = __expf(a);
    float s = e;

    float acc[8] = {0, 0, 0, 0, 0, 0, 0, 0};
    {
        float4 raw = *(const float4*)(xtb + ((unsigned)n << 9) + loff);
        acc_row(raw, e, acc);
    }

    int beg = g_off[n];
    int end = g_off[n + 1];
    for (int p = beg; p < end; p += 4) {
        int4 sv = *(const int4*)(g_csr + p);
        float a0 = *(const float*)(asb + (((unsigned)sv.x << 5) + hoff)) + ad_h;
        float a1 = *(const float*)(asb + (((unsigned)sv.y << 5) + hoff)) + ad_h;
        float a2 = *(const float*)(asb + (((unsigned)sv.z << 5) + hoff)) + ad_h;
        float a3 = *(const float*)(asb + (((unsigned)sv.w << 5) + hoff)) + ad_h;
        a0 = (a0 > 0.0f) ? a0 : NEG_SLOPE * a0;
        a1 = (a1 > 0.0f) ? a1 : NEG_SLOPE * a1;
        a2 = (a2 > 0.0f) ? a2 : NEG_SLOPE * a2;
        a3 = (a3 > 0.0f) ? a3 : NEG_SLOPE * a3;
        float e0 = __expf(a0);
        float e1 = __expf(a1);
        float e2 = __expf(a2);
        float e3 = __expf(a3);
        s += (e0 + e1) + (e2 + e3);
        float4 r0 = *(const float4*)(xtb + ((unsigned)sv.x << 9) + loff);
        float4 r1 = *(const float4*)(xtb + ((unsigned)sv.y << 9) + loff);
        float4 r2 = *(const float4*)(xtb + ((unsigned)sv.z << 9) + loff);
        float4 r3 = *(const float4*)(xtb + ((unsigned)sv.w << 9) + loff);
        acc_row(r0, e0, acc);
        acc_row(r1, e1, acc);
        acc_row(r2, e2, acc);
        acc_row(r3, e3, acc);
    }

    float inv = 1.0f / (s + 1e-16f);
    float r[8];
#pragma unroll
    for (int i = 0; i < 8; i++) r[i] = acc[i] * inv;

#pragma unroll
    for (int i = 0; i < 8; i++) {
        r[i] += __shfl_xor_sync(0xffffffffu, r[i], 4);
        r[i] += __shfl_xor_sync(0xffffffffu, r[i], 8);
        r[i] += __shfl_xor_sync(0xffffffffu, r[i], 16);
    }

    if (lane < 4) {
        float o[8];
#pragma unroll
        for (int i = 0; i < 8; i++) {
            float v = r[i] * 0.125f + bias[lane * 8 + i];
            o[i] = (v > 0.0f) ? v : 0.0f;
        }
        float4* orow = (float4*)(out + (size_t)n * C + lane * 8);
        orow[0] = make_float4(o[0], o[1], o[2], o[3]);
        orow[1] = make_float4(o[4], o[5], o[6], o[7]);
    }
}

// ---------------- launch: init, count, scan, gemm(slot4, s2), scatter, agg ----------------
extern "C" void kernel_launch(void* const* d_in, const int* in_sizes, int n_in,
                              void* d_out, int out_size) {
    const float* x       = (const float*)d_in[0];
    const void*  ei      = d_in[1];
    const float* W       = (const float*)d_in[2];
    const float* att_src = (const float*)d_in[3];
    const float* att_dst = (const float*)d_in[4];
    const float* bias    = (const float*)d_in[5];

    int N = in_sizes[0] / F_IN;
    int E = in_sizes[1] / 2;
    int n_check = E > 64 ? 64 : E;

    int initT = N + 1;
    if (initT < 8192) initT = 8192;

    // (1) init
    init_kernel<<<(initT + 255) / 256, 256>>>((const int*)ei, n_check, W, N);
    cudaEventRecord(g_hx.evFork, 0);

    // (2) count, (3) scan  [main stream]
    count_kernel<<<(E + 255) / 256, 256>>>(ei, E);
    int NB = (N + SCHUNK - 1) / SCHUNK;
    scan_kernel<<<NB, 256>>>(N);

    // (4) gemm on side stream — profile slot 4; overlaps count/scan/scatter
    cudaStreamWaitEvent(g_hx.s2, g_hx.evFork, 0);
    gemm_alpha_kernel<<<(N + MROWS - 1) / MROWS, 256, 0, g_hx.s2>>>(x, att_src, att_dst, N);
    cudaEventRecord(g_hx.evJoin, g_hx.s2);

    // (5) scatter [main stream]
    scatter_kernel<<<(E + 255) / 256, 256>>>(ei, E);

    // (6) aggregate (joins gemm)
    cudaStreamWaitEvent(0, g_hx.evJoin, 0);
    agg_kernel<<<(N + 7) / 8, 256>>>(bias, (float*)d_out, N);
}